// round 15
// baseline (speedup 1.0000x reference)
#include <cuda_runtime.h>
#include <cuda_bf16.h>

// Problem constants (fixed by reference setup_inputs)
#define B_   4
#define C_   32
#define H_   96
#define W_   312
#define D_   48
#define HW_  (H_ * W_)
#define W4_  (W_ / 4)           // 78 float4 per row
#define ROWS 12                 // h-rows per tile (span 14976B per d-plane)
#define NTHREADS 1024           // 12*78 = 936 active compute lanes
#define DHALF_Q 6               // 6 q-groups (24 disparities) per block
#define PAD_F 52                // front pad (floats): covers w-4q-4 >= -48
#define RPITCH (PAD_F + W_)     // 364 floats per row
#define PAD_VALUE 1.0f

// R14 structure with ROWS pushed to 12 under the 1024-thread block cap:
// 14976B contiguous store span per d-plane (vs 9984B). Active lanes/SM are
// unchanged (2 x 936 = 1872, same as 6 x 312 / 3 x 624); grid 2048 @ 296
// resident -> 6.92 waves (same ~1% tail). Sliding register window over a
// single shared r copy; division-free fill; __stcs streaming stores
// (A/B-confirmed vs write-back).
__global__ __launch_bounds__(NTHREADS) void cost_volume_kernel(
    const float* __restrict__ l_fmap,
    const float* __restrict__ r_fmap,
    float* __restrict__ out)
{
    const int bid  = blockIdx.x;            // 0 .. 2047
    const int half = bid & 1;               // D-half: q in [6*half, 6*half+6)
    const int tile = bid >> 1;              // 0 .. 1023
    const int hb   = tile % (H_ / ROWS);    // 8 row-groups
    const int bc   = tile / (H_ / ROWS);
    const int h0   = hb * ROWS;
    const int q0   = half * DHALF_Q;

    __shared__ float rbuf[ROWS][RPITCH];

    const long long in_off = (long long)bc * HW_ + (long long)h0 * W_;
    const float* r_g = r_fmap + in_off;

    const int tid = threadIdx.x;

    // Fill: thread tid (<312) owns column tid of all 12 rows; zero the pad.
    if (tid < W_) {
        #pragma unroll
        for (int rr = 0; rr < ROWS; ++rr)
            rbuf[rr][PAD_F + tid] = r_g[rr * W_ + tid];
        if (tid < PAD_F) {
            #pragma unroll
            for (int rr = 0; rr < ROWS; ++rr)
                rbuf[rr][tid] = 0.0f;       // masked anyway
        }
    }
    __syncthreads();

    if (tid >= ROWS * W4_) return;          // 936 active lanes
    const int row = tid / W4_;
    const int w4  = tid - row * W4_;
    const int w   = w4 * 4;

    const float4 l4 = *reinterpret_cast<const float4*>(
        l_fmap + in_off + row * W_ + w);

    // Output [B, C, D, H, W]: base for (bc, h0+row, w); per-d stride HW_
    float* outp = out + (long long)bc * (D_ * HW_)
                      + (long long)(h0 + row) * W_ + w;

    const float* rrow = &rbuf[row][0];

    // hi = quad(w - 4*q0); per group load lo = quad(w - 4*q - 4), then hi<-lo
    float4 hi = *reinterpret_cast<const float4*>(rrow + PAD_F + w - 4 * q0);

    #pragma unroll
    for (int qq = 0; qq < DHALF_Q; ++qq) {
        const int q = q0 + qq;
        const float4 lo = *reinterpret_cast<const float4*>(
            rrow + PAD_F + w - 4 * q - 4);

        {   // s = 0 : window = {hi.x, hi.y, hi.z, hi.w}
            const int d = 4 * q;
            float4 v;
            v.x = (w + 0 >= d) ? (l4.x - hi.x) : PAD_VALUE;
            v.y = (w + 1 >= d) ? (l4.y - hi.y) : PAD_VALUE;
            v.z = (w + 2 >= d) ? (l4.z - hi.z) : PAD_VALUE;
            v.w = (w + 3 >= d) ? (l4.w - hi.w) : PAD_VALUE;
            __stcs(reinterpret_cast<float4*>(outp + (long long)d * HW_), v);
        }
        {   // s = 1 : window = {lo.w, hi.x, hi.y, hi.z}
            const int d = 4 * q + 1;
            float4 v;
            v.x = (w + 0 >= d) ? (l4.x - lo.w) : PAD_VALUE;
            v.y = (w + 1 >= d) ? (l4.y - hi.x) : PAD_VALUE;
            v.z = (w + 2 >= d) ? (l4.z - hi.y) : PAD_VALUE;
            v.w = (w + 3 >= d) ? (l4.w - hi.z) : PAD_VALUE;
            __stcs(reinterpret_cast<float4*>(outp + (long long)d * HW_), v);
        }
        {   // s = 2 : window = {lo.z, lo.w, hi.x, hi.y}
            const int d = 4 * q + 2;
            float4 v;
            v.x = (w + 0 >= d) ? (l4.x - lo.z) : PAD_VALUE;
            v.y = (w + 1 >= d) ? (l4.y - lo.w) : PAD_VALUE;
            v.z = (w + 2 >= d) ? (l4.z - hi.x) : PAD_VALUE;
            v.w = (w + 3 >= d) ? (l4.w - hi.y) : PAD_VALUE;
            __stcs(reinterpret_cast<float4*>(outp + (long long)d * HW_), v);
        }
        {   // s = 3 : window = {lo.y, lo.z, lo.w, hi.x}
            const int d = 4 * q + 3;
            float4 v;
            v.x = (w + 0 >= d) ? (l4.x - lo.y) : PAD_VALUE;
            v.y = (w + 1 >= d) ? (l4.y - lo.z) : PAD_VALUE;
            v.z = (w + 2 >= d) ? (l4.z - lo.w) : PAD_VALUE;
            v.w = (w + 3 >= d) ? (l4.w - hi.x) : PAD_VALUE;
            __stcs(reinterpret_cast<float4*>(outp + (long long)d * HW_), v);
        }

        hi = lo;
    }
}

extern "C" void kernel_launch(void* const* d_in, const int* in_sizes, int n_in,
                              void* d_out, int out_size)
{
    const float* l_fmap = (const float*)d_in[0];
    const float* r_fmap = (const float*)d_in[1];
    float* out = (float*)d_out;

    const int blocks = B_ * C_ * (H_ / ROWS) * 2;   // 2048
    cost_volume_kernel<<<blocks, NTHREADS>>>(l_fmap, r_fmap, out);
}

// round 16
// speedup vs baseline: 1.0307x; 1.0307x over previous
#include <cuda_runtime.h>
#include <cuda_bf16.h>

// Problem constants (fixed by reference setup_inputs)
#define B_   4
#define C_   32
#define H_   96
#define W_   312
#define D_   48
#define HW_  (H_ * W_)
#define W4_  (W_ / 4)           // 78 float4 per row
#define ROWS 8                  // h-rows per tile (measured optimum)
#define NTHREADS 640            // 8*78 = 624 active compute lanes
#define DHALF_Q 6               // 6 q-groups (24 disparities) per block
#define PAD_F 52                // front pad (floats): covers w-4q-4 >= -48
#define RPITCH (PAD_F + W_)     // 364 floats per row
#define PAD_VALUE 1.0f

// FINAL (R14 config, best measured 122.9us):
//  - one block per (bc, 8-row group, D-half); grid 3072 @ 444 resident ->
//    6.92 waves (~1% tail)
//  - 9984B contiguous store span per d-plane (span sweep: 4992B=125.0us,
//    9984B=122.9us, 14976B=126.7us -> interior optimum)
//  - sliding register window over a single shared r copy: 1 conflict-free
//    LDS.128 per 4 disparities
//  - division-free fill (thread t owns column t of all 8 rows)
//  - __stcs streaming float4 stores (A/B: 125.0us vs 131.1us write-back)
__global__ __launch_bounds__(NTHREADS) void cost_volume_kernel(
    const float* __restrict__ l_fmap,
    const float* __restrict__ r_fmap,
    float* __restrict__ out)
{
    const int bid  = blockIdx.x;            // 0 .. 3071
    const int half = bid & 1;               // D-half: q in [6*half, 6*half+6)
    const int tile = bid >> 1;              // 0 .. 1535
    const int hb   = tile % (H_ / ROWS);    // 12 row-groups
    const int bc   = tile / (H_ / ROWS);
    const int h0   = hb * ROWS;
    const int q0   = half * DHALF_Q;

    __shared__ float rbuf[ROWS][RPITCH];

    const long long in_off = (long long)bc * HW_ + (long long)h0 * W_;
    const float* r_g = r_fmap + in_off;

    const int tid = threadIdx.x;

    // Fill: thread tid (<312) owns column tid of all 8 rows; zero the pad.
    if (tid < W_) {
        #pragma unroll
        for (int rr = 0; rr < ROWS; ++rr)
            rbuf[rr][PAD_F + tid] = r_g[rr * W_ + tid];
        if (tid < PAD_F) {
            #pragma unroll
            for (int rr = 0; rr < ROWS; ++rr)
                rbuf[rr][tid] = 0.0f;       // masked anyway
        }
    }
    __syncthreads();

    if (tid >= ROWS * W4_) return;          // 624 active lanes
    const int row = tid / W4_;
    const int w4  = tid - row * W4_;
    const int w   = w4 * 4;

    const float4 l4 = *reinterpret_cast<const float4*>(
        l_fmap + in_off + row * W_ + w);

    // Output [B, C, D, H, W]: base for (bc, h0+row, w); per-d stride HW_
    float* outp = out + (long long)bc * (D_ * HW_)
                      + (long long)(h0 + row) * W_ + w;

    const float* rrow = &rbuf[row][0];

    // hi = quad(w - 4*q0); per group load lo = quad(w - 4*q - 4), then hi<-lo
    float4 hi = *reinterpret_cast<const float4*>(rrow + PAD_F + w - 4 * q0);

    #pragma unroll
    for (int qq = 0; qq < DHALF_Q; ++qq) {
        const int q = q0 + qq;
        const float4 lo = *reinterpret_cast<const float4*>(
            rrow + PAD_F + w - 4 * q - 4);

        {   // s = 0 : window = {hi.x, hi.y, hi.z, hi.w}
            const int d = 4 * q;
            float4 v;
            v.x = (w + 0 >= d) ? (l4.x - hi.x) : PAD_VALUE;
            v.y = (w + 1 >= d) ? (l4.y - hi.y) : PAD_VALUE;
            v.z = (w + 2 >= d) ? (l4.z - hi.z) : PAD_VALUE;
            v.w = (w + 3 >= d) ? (l4.w - hi.w) : PAD_VALUE;
            __stcs(reinterpret_cast<float4*>(outp + (long long)d * HW_), v);
        }
        {   // s = 1 : window = {lo.w, hi.x, hi.y, hi.z}
            const int d = 4 * q + 1;
            float4 v;
            v.x = (w + 0 >= d) ? (l4.x - lo.w) : PAD_VALUE;
            v.y = (w + 1 >= d) ? (l4.y - hi.x) : PAD_VALUE;
            v.z = (w + 2 >= d) ? (l4.z - hi.y) : PAD_VALUE;
            v.w = (w + 3 >= d) ? (l4.w - hi.z) : PAD_VALUE;
            __stcs(reinterpret_cast<float4*>(outp + (long long)d * HW_), v);
        }
        {   // s = 2 : window = {lo.z, lo.w, hi.x, hi.y}
            const int d = 4 * q + 2;
            float4 v;
            v.x = (w + 0 >= d) ? (l4.x - lo.z) : PAD_VALUE;
            v.y = (w + 1 >= d) ? (l4.y - lo.w) : PAD_VALUE;
            v.z = (w + 2 >= d) ? (l4.z - hi.x) : PAD_VALUE;
            v.w = (w + 3 >= d) ? (l4.w - hi.y) : PAD_VALUE;
            __stcs(reinterpret_cast<float4*>(outp + (long long)d * HW_), v);
        }
        {   // s = 3 : window = {lo.y, lo.z, lo.w, hi.x}
            const int d = 4 * q + 3;
            float4 v;
            v.x = (w + 0 >= d) ? (l4.x - lo.y) : PAD_VALUE;
            v.y = (w + 1 >= d) ? (l4.y - lo.z) : PAD_VALUE;
            v.z = (w + 2 >= d) ? (l4.z - lo.w) : PAD_VALUE;
            v.w = (w + 3 >= d) ? (l4.w - hi.x) : PAD_VALUE;
            __stcs(reinterpret_cast<float4*>(outp + (long long)d * HW_), v);
        }

        hi = lo;
    }
}

extern "C" void kernel_launch(void* const* d_in, const int* in_sizes, int n_in,
                              void* d_out, int out_size)
{
    const float* l_fmap = (const float*)d_in[0];
    const float* r_fmap = (const float*)d_in[1];
    float* out = (float*)d_out;

    const int blocks = B_ * C_ * (H_ / ROWS) * 2;   // 3072
    cost_volume_kernel<<<blocks, NTHREADS>>>(l_fmap, r_fmap, out);
}